// round 3
// baseline (speedup 1.0000x reference)
#include <cuda_runtime.h>

// Problem constants (from reference)
#define VOCAB   512
#define MAXLEN  512
#define BATCH   128
#define NFEAT   (VOCAB + VOCAB * VOCAB + 2)   // 262658

// One CTA per batch row, 256 threads, TWO positions per thread via one float4
// load (positions 2t, 2t+1). Per thread:
//   unigram W[a0], W[a1] and intra-pair bigram W[V + a0*512 + a1] issue
//   immediately after the x load (no shuffle on critical path);
//   cross-pair bigram needs neighbor's a0 via shfl_down (lane 31: direct load).
__global__ __launch_bounds__(256, 4)
void lr_ngram_kernel(const float* __restrict__ x,
                     const int*   __restrict__ lengths,
                     const float* __restrict__ W,
                     const float* __restrict__ bias,
                     float*       __restrict__ out)
{
    __shared__ float s_sum[8];
    __shared__ float s_max[8];

    const int b    = blockIdx.x;
    const int t    = threadIdx.x;          // 0..255
    const int lane = t & 31;
    const int wid  = t >> 5;
    const int len  = lengths[b];

    const int p0 = 2 * t;                  // positions 2t, 2t+1
    const float4* __restrict__ xrow =
        reinterpret_cast<const float4*>(x + (size_t)b * MAXLEN * 2);

    // One 16B load: (a0, t0, a1, t1)
    float4 v = xrow[t];
    int a0 = (int)v.x;
    int a1 = (int)v.z;

    // Gathers with no shuffle dependency — issue right away.
    float sum = 0.0f;
    if (p0     < len) sum += W[a0];
    if (p0 + 1 < len) sum += W[a1];
    if (p0 + 1 < len) sum += W[VOCAB + (a0 << 9) + a1];

    // Cross-pair bigram: (2t+1, 2t+2). Neighbor a0 via shuffle; warp edge loads.
    int a2 = __shfl_down_sync(0xffffffffu, a0, 1);
    if (lane == 31 && p0 + 2 < MAXLEN)
        a2 = (int)__ldg(&x[(size_t)b * MAXLEN * 2 + (p0 + 2) * 2]);
    if (p0 + 2 < len) sum += W[VOCAB + (a1 << 9) + a2];

    // Masked time max over the two owned positions.
    float tmax = -3.402823466e38f;
    if (p0     < len) tmax = v.y;
    if (p0 + 1 < len) tmax = fmaxf(tmax, v.w);

    // Warp reduction.
    const unsigned m = 0xffffffffu;
    #pragma unroll
    for (int off = 16; off > 0; off >>= 1) {
        sum  += __shfl_down_sync(m, sum, off);
        tmax  = fmaxf(tmax, __shfl_down_sync(m, tmax, off));
    }
    if (lane == 0) { s_sum[wid] = sum; s_max[wid] = tmax; }
    __syncthreads();

    // Final reduction across 8 warps by warp 0.
    if (wid == 0) {
        sum  = (lane < 8) ? s_sum[lane] : 0.0f;
        tmax = (lane < 8) ? s_max[lane] : -3.402823466e38f;
        #pragma unroll
        for (int off = 4; off > 0; off >>= 1) {
            sum  += __shfl_down_sync(m, sum, off);
            tmax  = fmaxf(tmax, __shfl_down_sync(m, tmax, off));
        }
        if (lane == 0) {
            out[b] = sum
                   + tmax * W[NFEAT - 2]
                   + (float)len * W[NFEAT - 1]
                   + bias[0];
        }
    }
}

extern "C" void kernel_launch(void* const* d_in, const int* in_sizes, int n_in,
                              void* d_out, int out_size)
{
    const float* x       = (const float*)d_in[0];   // [B, MAXLEN, 2] f32
    const int*   lengths = (const int*)  d_in[1];   // [B] i32
    const float* W       = (const float*)d_in[2];   // [1, F] f32
    const float* bias    = (const float*)d_in[3];   // [1] f32
    float*       out     = (float*)d_out;           // [B, 1] f32

    lr_ngram_kernel<<<BATCH, 256>>>(x, lengths, W, bias, out);
}

// round 4
// speedup vs baseline: 1.0141x; 1.0141x over previous
#include <cuda_runtime.h>

// Problem constants (from reference)
#define VOCAB   512
#define MAXLEN  512
#define BATCH   128
#define NFEAT   (VOCAB + VOCAB * VOCAB + 2)   // 262658

// One CTA per batch row, 1024 threads (32 warps) for maximum latency hiding
// of the random W gathers (the measured bottleneck).
//   threads 0..511   : position j = t      -> unigram W[a_j], masked time-max
//   threads 512..1023: position p = t-512  -> bigram  W[V + a_p*512 + a_{p+1}]
// Every thread: one 8B x load + at most one 4B gather. Neighbor action for
// bigram threads comes from shfl_down within the warp (lane 31: direct 4B load).
__global__ __launch_bounds__(1024, 1)
void lr_ngram_kernel(const float* __restrict__ x,
                     const int*   __restrict__ lengths,
                     const float* __restrict__ W,
                     const float* __restrict__ bias,
                     float*       __restrict__ out)
{
    __shared__ float s_sum[32];
    __shared__ float s_max[32];

    const int b    = blockIdx.x;
    const int t    = threadIdx.x;          // 0..1023
    const int lane = t & 31;
    const int wid  = t >> 5;
    const int len  = lengths[b];

    const float* __restrict__ xr = x + (size_t)b * MAXLEN * 2;

    float sum  = 0.0f;
    float tmax = -3.402823466e38f;

    if (t < MAXLEN) {
        // Unigram + time role.
        const int j = t;
        float2 at = reinterpret_cast<const float2*>(xr)[j];
        if (j < len) {
            sum  = W[(int)at.x];
            tmax = at.y;
        }
    } else {
        // Bigram role.
        const int p = t - MAXLEN;          // 0..511, pair (p, p+1)
        float2 at = reinterpret_cast<const float2*>(xr)[p];
        int a  = (int)at.x;
        int an = __shfl_down_sync(0xffffffffu, a, 1);
        if (lane == 31 && p + 1 < MAXLEN)
            an = (int)__ldg(&xr[(p + 1) * 2]);
        if (p + 1 < len)
            sum = W[VOCAB + (a << 9) + an];
    }

    // Warp reduction (sum + max together).
    const unsigned m = 0xffffffffu;
    #pragma unroll
    for (int off = 16; off > 0; off >>= 1) {
        sum  += __shfl_down_sync(m, sum, off);
        tmax  = fmaxf(tmax, __shfl_down_sync(m, tmax, off));
    }
    if (lane == 0) { s_sum[wid] = sum; s_max[wid] = tmax; }
    __syncthreads();

    // Final reduction across 32 warps by warp 0.
    if (wid == 0) {
        sum  = s_sum[lane];
        tmax = s_max[lane];
        #pragma unroll
        for (int off = 16; off > 0; off >>= 1) {
            sum  += __shfl_down_sync(m, sum, off);
            tmax  = fmaxf(tmax, __shfl_down_sync(m, tmax, off));
        }
        if (lane == 0) {
            out[b] = sum
                   + tmax * W[NFEAT - 2]
                   + (float)len * W[NFEAT - 1]
                   + bias[0];
        }
    }
}

extern "C" void kernel_launch(void* const* d_in, const int* in_sizes, int n_in,
                              void* d_out, int out_size)
{
    const float* x       = (const float*)d_in[0];   // [B, MAXLEN, 2] f32
    const int*   lengths = (const int*)  d_in[1];   // [B] i32
    const float* W       = (const float*)d_in[2];   // [1, F] f32
    const float* bias    = (const float*)d_in[3];   // [1] f32
    float*       out     = (float*)d_out;           // [B, 1] f32

    lr_ngram_kernel<<<BATCH, 1024>>>(x, lengths, W, bias, out);
}

// round 5
// speedup vs baseline: 1.0588x; 1.0441x over previous
#include <cuda_runtime.h>

// Problem constants (from reference)
#define VOCAB   512
#define MAXLEN  512
#define BATCH   128
#define NFEAT   (VOCAB + VOCAB * VOCAB + 2)   // 262658

// One CTA per batch row, 512 threads, one position per thread (best measured
// shape). Critical-path refinement: the neighbor action a_{j+1} is loaded
// directly (4B, independent of the 8B x load) instead of via shfl, so the
// bigram gather waits on max(two parallel loads), not load -> shfl -> gather.
__global__ __launch_bounds__(512, 2)
void lr_ngram_kernel(const float* __restrict__ x,
                     const int*   __restrict__ lengths,
                     const float* __restrict__ W,
                     const float* __restrict__ bias,
                     float*       __restrict__ out)
{
    __shared__ float s_sum[16];
    __shared__ float s_max[16];

    const int b    = blockIdx.x;
    const int j    = threadIdx.x;          // position, 0..511
    const int lane = j & 31;
    const int wid  = j >> 5;
    const int len  = lengths[b];

    const float* __restrict__ xr = x + (size_t)b * MAXLEN * 2;

    // Two independent loads, issued back-to-back.
    float2 at = reinterpret_cast<const float2*>(xr)[j];      // (a_j, t_j)
    float  anf = (j + 1 < MAXLEN) ? __ldg(&xr[(j + 1) * 2]) : 0.0f;  // a_{j+1}

    int a  = (int)at.x;
    int an = (int)anf;

    // Gathers: unigram + bigram, independent of each other.
    float sum = 0.0f;
    if (j < len)     sum += W[a];
    if (j + 1 < len) sum += W[VOCAB + (a << 9) + an];

    float tmax = (j < len) ? at.y : -3.402823466e38f;

    // Warp reduction (sum + max together).
    const unsigned m = 0xffffffffu;
    #pragma unroll
    for (int off = 16; off > 0; off >>= 1) {
        sum  += __shfl_down_sync(m, sum, off);
        tmax  = fmaxf(tmax, __shfl_down_sync(m, tmax, off));
    }
    if (lane == 0) { s_sum[wid] = sum; s_max[wid] = tmax; }
    __syncthreads();

    // Final reduction across 16 warps by warp 0.
    if (wid == 0) {
        sum  = (lane < 16) ? s_sum[lane] : 0.0f;
        tmax = (lane < 16) ? s_max[lane] : -3.402823466e38f;
        #pragma unroll
        for (int off = 8; off > 0; off >>= 1) {
            sum  += __shfl_down_sync(m, sum, off);
            tmax  = fmaxf(tmax, __shfl_down_sync(m, tmax, off));
        }
        if (lane == 0) {
            out[b] = sum
                   + tmax * W[NFEAT - 2]
                   + (float)len * W[NFEAT - 1]
                   + bias[0];
        }
    }
}

extern "C" void kernel_launch(void* const* d_in, const int* in_sizes, int n_in,
                              void* d_out, int out_size)
{
    const float* x       = (const float*)d_in[0];   // [B, MAXLEN, 2] f32
    const int*   lengths = (const int*)  d_in[1];   // [B] i32
    const float* W       = (const float*)d_in[2];   // [1, F] f32
    const float* bias    = (const float*)d_in[3];   // [1] f32
    float*       out     = (float*)d_out;           // [B, 1] f32

    lr_ngram_kernel<<<BATCH, 512>>>(x, lengths, W, bias, out);
}